// round 14
// baseline (speedup 1.0000x reference)
#include <cuda_runtime.h>
#include <cuda_fp16.h>
#include <math.h>

// Problem constants
#define B_SZ   8
#define N_SZ   4096
#define E_SZ   131072
#define F_SZ   64
#define ALPHA  0.2f
#define CAP    128        // per-node bucket capacity (deg ~ Poisson(32))

#define GEMM_BLOCKS 256   // 128 rows per block (two 64-row tiles)
#define SCAT_BLOCKS 128   // E / (256*4)

// packed fp32x2 FMA (sm_103a FFMA2; only reachable via PTX)
#define FMA2(acc, va, vb) \
    asm("fma.rn.f32x2 %0, %1, %2, %0;" : "+l"(acc) : "l"(va), "l"(vb))

// ---------------- scratch (device globals; no allocation allowed) ----------
// NOTE: zero-initialized at module load; k_main re-zeroes g_count each call.
__device__ __half2 g_Wh2[(size_t)B_SZ * N_SZ * 32];   // Wh in fp16, 4 MB
__device__ float   g_ssrc[B_SZ * N_SZ];
__device__ float   g_sdst[B_SZ * N_SZ];
__device__ int     g_count[N_SZ];
__device__ int2    g_edge[N_SZ * CAP];                // (dst, weight) by src

// ---------------- kernel 1 (fused): GEMM+scores  |  edge scatter -----------
// Blocks [0, 256): Wh = h @ W via packed f32x2 FMAs. SIMD lanes carry
//   even-k / odd-k partial sums (combined in epilogue - pure reassociation).
//   A pairs come free from As[row][k] (k-contiguous); W staged transposed
//   (Wt[c][k]) so B pairs are also contiguous. Thread columns c = tx + 16j
//   make the Wt loads bank-conflict-free.
// Blocks [256, 384): bucketed edge scatter.
__global__ void __launch_bounds__(256) k_fused(const float* __restrict__ h,
                                               const float* __restrict__ W,
                                               const float* __restrict__ a,
                                               const int*   __restrict__ ei,
                                               const float* __restrict__ ew) {
    const int tid = threadIdx.x;

    if (blockIdx.x >= GEMM_BLOCKS) {
        // ---- scatter path: interleaved (dst, weight) 8B stores ----
        const int sc = blockIdx.x - GEMM_BLOCKS;
        const int v  = sc * 256 + tid;                 // vec4 index
        int4   s4 = ((const int4*)  ei)[v];
        int4   d4 = ((const int4*) (ei + E_SZ))[v];
        float4 w4 = ((const float4*)ew)[v];
#pragma unroll
        for (int j = 0; j < 4; j++) {
            int s = (&s4.x)[j];
            int p = atomicAdd(&g_count[s], 1);
            if (p < CAP)
                g_edge[s * CAP + p] = make_int2((&d4.x)[j],
                                                __float_as_int((&w4.x)[j]));
        }
        return;
    }

    // ---- GEMM path ----
    __shared__ float As[64][68];     // h tile, k-contiguous rows
    __shared__ float Wt[64][68];     // W TRANSPOSED: Wt[c][k], k-contiguous
    __shared__ float sA[128];

    if (tid < 128) sA[tid] = a[tid];
    // stage W transposed (one-time scattered STS.32s)
    for (int i = tid; i < 1024; i += 256) {      // float4 index over W
        int k = i >> 4, c4 = i & 15;
        float4 v = ((const float4*)W)[i];
        Wt[c4 * 4 + 0][k] = v.x;
        Wt[c4 * 4 + 1][k] = v.y;
        Wt[c4 * 4 + 2][k] = v.z;
        Wt[c4 * 4 + 3][k] = v.w;
    }

    const int tx = tid & 15, ty = tid >> 4;   // 16x16 threads
    __half* const gw = (__half*)g_Wh2;

#pragma unroll
    for (int half = 0; half < 2; half++) {
        const int row0 = blockIdx.x * 128 + half * 64;

        if (half) __syncthreads();           // readers done with prev As
        for (int i = tid; i < 1024; i += 256) {
            int r = i >> 4, f4 = i & 15;
            float4 v = ((const float4*)(h + (size_t)(row0 + r) * 64))[f4];
            *(float4*)&As[r][f4 * 4] = v;
        }
        __syncthreads();

        // acc2[i][j]: packed pair = (even-k partial, odd-k partial)
        unsigned long long acc2[4][4];
#pragma unroll
        for (int i = 0; i < 4; i++)
#pragma unroll
            for (int j = 0; j < 4; j++) acc2[i][j] = 0ULL;

#pragma unroll
        for (int k0 = 0; k0 < 64; k0 += 4) {
            ulonglong2 av[4], bv[4];
#pragma unroll
            for (int i = 0; i < 4; i++)      // broadcast LDS.128 (A rows)
                av[i] = *(const ulonglong2*)&As[ty * 4 + i][k0];
#pragma unroll
            for (int j = 0; j < 4; j++)      // conflict-free LDS.128 (W cols)
                bv[j] = *(const ulonglong2*)&Wt[tx + 16 * j][k0];
#pragma unroll
            for (int i = 0; i < 4; i++)
#pragma unroll
                for (int j = 0; j < 4; j++) {
                    FMA2(acc2[i][j], av[i].x, bv[j].x);  // k0,k0+1
                    FMA2(acc2[i][j], av[i].y, bv[j].y);  // k0+2,k0+3
                }
        }

#pragma unroll
        for (int i = 0; i < 4; i++) {
            const int row = row0 + ty * 4 + i;
            float accf[4];
#pragma unroll
            for (int j = 0; j < 4; j++) {
                float lo = __uint_as_float((unsigned)acc2[i][j]);
                float hi = __uint_as_float((unsigned)(acc2[i][j] >> 32));
                accf[j] = lo + hi;
            }
            // Wh fp16 store: this thread owns columns tx + 16j
#pragma unroll
            for (int j = 0; j < 4; j++)
                gw[(size_t)row * 64 + tx + 16 * j] = __float2half_rn(accf[j]);

            // scores (columns tx + 16j)
            float s1 = accf[0] * sA[tx] + accf[1] * sA[tx + 16]
                     + accf[2] * sA[tx + 32] + accf[3] * sA[tx + 48];
            float s2 = accf[0] * sA[64 + tx] + accf[1] * sA[64 + tx + 16]
                     + accf[2] * sA[64 + tx + 32] + accf[3] * sA[64 + tx + 48];
#pragma unroll
            for (int o = 8; o > 0; o >>= 1) {   // reduce within 16-lane group
                s1 += __shfl_xor_sync(0xffffffffu, s1, o);
                s2 += __shfl_xor_sync(0xffffffffu, s2, o);
            }
            if (tx == 0) { g_ssrc[row] = s1; g_sdst[row] = s2; }
        }
    }
}

// ---------------- kernel 2: per-node softmax aggregation (R9 winner) -------
// One block per node n; warp b handles batch b.
// Pass A: p = exp(lrelu(ssrc+sdst)*w)  (no max pass; |e| small, no overflow).
// Pass B: 8 edges per iteration, 4 LDG.64s in flight, two accumulator chains.
__global__ void __launch_bounds__(256) k_main(float* __restrict__ out) {
    const int n    = blockIdx.x;
    const int b    = threadIdx.x >> 5;
    const int lane = threadIdx.x & 31;

    __shared__ int2 s_dw[CAP];
    __shared__ int2 s_dp[B_SZ][CAP + 8];

    const int deg = min(g_count[n], CAP);   // read BEFORE reset

    for (int i = threadIdx.x; i < deg; i += 256)
        s_dw[i] = g_edge[n * CAP + i];
    __syncthreads();
    if (threadIdx.x == 0) g_count[n] = 0;   // reset for next graph replay

    const float ssrc = g_ssrc[b * N_SZ + n];
    const float* __restrict__ sd = &g_sdst[b * N_SZ];

    // ---- pass A: attention weights (lane-strided) ----
    float denom = 0.f;
    for (int k = lane; k < deg; k += 32) {
        int2  dw = s_dw[k];
        float e  = ssrc + __ldg(&sd[dw.x]);
        e = fmaxf(e, ALPHA * e) * __int_as_float(dw.y);   // leaky relu * w
        float p = __expf(e);
        denom += p;
        s_dp[b][k] = make_int2(dw.x * 128, __float_as_int(p));
    }
#pragma unroll
    for (int o = 16; o > 0; o >>= 1)
        denom += __shfl_xor_sync(0xffffffffu, denom, o);
    if (lane < 8) s_dp[b][deg + lane] = make_int2(0, 0);  // pad: no tail loop
    __syncwarp();

    // ---- pass B: 8 edges/iter, 16 lanes/edge, 4x LDG.64 in flight ----
    const int  sub  = lane >> 4;            // 0: even edge, 1: odd edge
    const char* base = (const char*)(g_Wh2 + (size_t)b * N_SZ * 32)
                     + (lane & 15) * 8;     // 8B fp16 feature slice
    float a0 = 0.f, a1 = 0.f, a2 = 0.f, a3 = 0.f;
    float c0 = 0.f, c1 = 0.f, c2 = 0.f, c3 = 0.f;
    for (int k = 0; k < deg; k += 8) {
        int2 dp0 = s_dp[b][k     + sub];
        int2 dp1 = s_dp[b][k + 2 + sub];
        int2 dp2 = s_dp[b][k + 4 + sub];
        int2 dp3 = s_dp[b][k + 6 + sub];
        uint2 r0 = *(const uint2*)(base + dp0.x);   // 4 independent LDG.64s
        uint2 r1 = *(const uint2*)(base + dp1.x);
        uint2 r2 = *(const uint2*)(base + dp2.x);
        uint2 r3 = *(const uint2*)(base + dp3.x);

        float p0 = __int_as_float(dp0.y);
        float2 f00 = __half22float2(*(const __half2*)&r0.x);
        float2 f01 = __half22float2(*(const __half2*)&r0.y);
        a0 += p0 * f00.x; a1 += p0 * f00.y;
        a2 += p0 * f01.x; a3 += p0 * f01.y;

        float p1 = __int_as_float(dp1.y);
        float2 f10 = __half22float2(*(const __half2*)&r1.x);
        float2 f11 = __half22float2(*(const __half2*)&r1.y);
        c0 += p1 * f10.x; c1 += p1 * f10.y;
        c2 += p1 * f11.x; c3 += p1 * f11.y;

        float p2 = __int_as_float(dp2.y);
        float2 f20 = __half22float2(*(const __half2*)&r2.x);
        float2 f21 = __half22float2(*(const __half2*)&r2.y);
        a0 += p2 * f20.x; a1 += p2 * f20.y;
        a2 += p2 * f21.x; a3 += p2 * f21.y;

        float p3 = __int_as_float(dp3.y);
        float2 f30 = __half22float2(*(const __half2*)&r3.x);
        float2 f31 = __half22float2(*(const __half2*)&r3.y);
        c0 += p3 * f30.x; c1 += p3 * f30.y;
        c2 += p3 * f31.x; c3 += p3 * f31.y;
    }
    a0 += c0; a1 += c1; a2 += c2; a3 += c3;

    // combine the two edge-subsets (lanes l and l+16 hold same features)
    a0 += __shfl_xor_sync(0xffffffffu, a0, 16);
    a1 += __shfl_xor_sync(0xffffffffu, a1, 16);
    a2 += __shfl_xor_sync(0xffffffffu, a2, 16);
    a3 += __shfl_xor_sync(0xffffffffu, a3, 16);

    if (lane < 16) {
        float r0 = 0.f, r1 = 0.f, r2 = 0.f, r3 = 0.f;
        if (deg > 0) {
            float inv = 1.f / denom;
            r0 = a0 * inv; r1 = a1 * inv; r2 = a2 * inv; r3 = a3 * inv;
        }
        // ELU tail: expm1f(x) == __expf(x)-1 to ~6e-8 abs near 0; cheaper
        r0 = r0 > 0.f ? r0 : __expf(r0) - 1.f;
        r1 = r1 > 0.f ? r1 : __expf(r1) - 1.f;
        r2 = r2 > 0.f ? r2 : __expf(r2) - 1.f;
        r3 = r3 > 0.f ? r3 : __expf(r3) - 1.f;
        *(float4*)&out[((size_t)b * N_SZ + n) * 64 + lane * 4]
            = make_float4(r0, r1, r2, r3);
    }
}

// ---------------- launch ---------------------------------------------------
extern "C" void kernel_launch(void* const* d_in, const int* in_sizes, int n_in,
                              void* d_out, int out_size) {
    const float* h  = (const float*)d_in[0];
    const int*   ei = (const int*)  d_in[1];
    const float* ew = (const float*)d_in[2];
    const float* W  = (const float*)d_in[3];
    const float* a  = (const float*)d_in[4];
    float* out = (float*)d_out;

    k_fused<<<GEMM_BLOCKS + SCAT_BLOCKS, 256>>>(h, W, a, ei, ew);
    k_main <<<N_SZ, 256>>>(out);
}

// round 15
// speedup vs baseline: 1.0780x; 1.0780x over previous
#include <cuda_runtime.h>
#include <cuda_fp16.h>
#include <math.h>

// Problem constants
#define B_SZ   8
#define N_SZ   4096
#define E_SZ   131072
#define F_SZ   64
#define ALPHA  0.2f
#define CAP    128        // per-node bucket capacity (deg ~ Poisson(32))

#define GEMM_BLOCKS 512
#define SCAT_BLOCKS 128   // E / (256*4)

// packed fp32x2 FMA (sm_103a FFMA2; only reachable via PTX)
#define FMA2(acc, va, vb) \
    asm("fma.rn.f32x2 %0, %1, %2, %0;" : "+l"(acc) : "l"(va), "l"(vb))
#define PACK2(dst, lo, hi) \
    asm("mov.b64 %0, {%1, %2};" : "=l"(dst) : "r"(__float_as_int(lo)), "r"(__float_as_int(hi)))

// ---------------- scratch (device globals; no allocation allowed) ----------
// NOTE: zero-initialized at module load; k_main re-zeroes g_count each call.
__device__ __half2 g_Wh2[(size_t)B_SZ * N_SZ * 32];   // Wh in fp16, 4 MB
__device__ float   g_ssrc[B_SZ * N_SZ];
__device__ float   g_sdst[B_SZ * N_SZ];
__device__ int     g_count[N_SZ];
__device__ int2    g_edge[N_SZ * CAP];                // (dst, weight) by src

// ---------------- kernel 1 (fused): GEMM+scores  |  edge scatter -----------
// Blocks [0, 512): Wh = h @ W (64-row tile). Mainloop uses packed f32x2 FMAs
//   with SIMD lanes = two adjacent OUTPUT COLUMNS, so B pairs come straight
//   from the existing Ws[k][tx*4..] LDS.128 and the epilogue/stores/scores
//   are bit-identical to the R9 FFMA version.
// Blocks [512, 640): bucketed edge scatter.
__global__ void __launch_bounds__(256) k_fused(const float* __restrict__ h,
                                               const float* __restrict__ W,
                                               const float* __restrict__ a,
                                               const int*   __restrict__ ei,
                                               const float* __restrict__ ew) {
    const int tid = threadIdx.x;

    if (blockIdx.x >= GEMM_BLOCKS) {
        // ---- scatter path: interleaved (dst, weight) 8B stores ----
        const int sc = blockIdx.x - GEMM_BLOCKS;
        const int v  = sc * 256 + tid;                 // vec4 index
        int4   s4 = ((const int4*)  ei)[v];
        int4   d4 = ((const int4*) (ei + E_SZ))[v];
        float4 w4 = ((const float4*)ew)[v];
#pragma unroll
        for (int j = 0; j < 4; j++) {
            int s = (&s4.x)[j];
            int p = atomicAdd(&g_count[s], 1);
            if (p < CAP)
                g_edge[s * CAP + p] = make_int2((&d4.x)[j],
                                                __float_as_int((&w4.x)[j]));
        }
        return;
    }

    // ---- GEMM path: Wh = h @ W (64-row tile), scores epilogue ----
    __shared__ float As[64][68];     // stride 68: float4-aligned k-chunks
    __shared__ float Ws[64][64];
    __shared__ float sA[128];
    const int row0 = blockIdx.x * 64;

    if (tid < 128) sA[tid] = a[tid];
    for (int i = tid; i < 1024; i += 256)
        ((float4*)Ws)[i] = ((const float4*)W)[i];
    for (int i = tid; i < 1024; i += 256) {
        int r = i >> 4, f4 = i & 15;
        float4 v = ((const float4*)(h + (size_t)(row0 + r) * 64))[f4];
        *(float4*)&As[r][f4 * 4] = v;
    }
    __syncthreads();

    const int tx = tid & 15, ty = tid >> 4;   // 16x16 threads, 4x4 microtile
    // acc2[i][j2]: packed pair of adjacent output columns (tx*4+2j2, +1)
    unsigned long long acc2[4][2];
#pragma unroll
    for (int i = 0; i < 4; i++) { acc2[i][0] = 0ULL; acc2[i][1] = 0ULL; }

#pragma unroll
    for (int k0 = 0; k0 < 64; k0 += 4) {
        float4 a4[4];
#pragma unroll
        for (int i = 0; i < 4; i++)
            a4[i] = *(const float4*)&As[ty * 4 + i][k0];   // broadcast LDS.128
#pragma unroll
        for (int kk = 0; kk < 4; kk++) {
            // 16B of Ws row = two packed column-pairs (same LDS as R9)
            ulonglong2 bv2 = *(const ulonglong2*)&Ws[k0 + kk][tx * 4];
#pragma unroll
            for (int i = 0; i < 4; i++) {
                float av = (&a4[i].x)[kk];
                unsigned long long av2;
                PACK2(av2, av, av);          // alu-pipe dup, overlaps fma pipe
                FMA2(acc2[i][0], av2, bv2.x);
                FMA2(acc2[i][1], av2, bv2.y);
            }
        }
    }

#pragma unroll
    for (int i = 0; i < 4; i++) {
        const int row = row0 + ty * 4 + i;
        float acc0 = __uint_as_float((unsigned)acc2[i][0]);
        float acc1 = __uint_as_float((unsigned)(acc2[i][0] >> 32));
        float acc2f = __uint_as_float((unsigned)acc2[i][1]);
        float acc3 = __uint_as_float((unsigned)(acc2[i][1] >> 32));

        __half2 h0 = __floats2half2_rn(acc0, acc1);
        __half2 h1 = __floats2half2_rn(acc2f, acc3);
        g_Wh2[(size_t)row * 32 + tx * 2 + 0] = h0;
        g_Wh2[(size_t)row * 32 + tx * 2 + 1] = h1;

        float s1 = acc0 * sA[tx * 4 + 0] + acc1 * sA[tx * 4 + 1]
                 + acc2f * sA[tx * 4 + 2] + acc3 * sA[tx * 4 + 3];
        float s2 = acc0 * sA[64 + tx * 4 + 0] + acc1 * sA[64 + tx * 4 + 1]
                 + acc2f * sA[64 + tx * 4 + 2] + acc3 * sA[64 + tx * 4 + 3];
#pragma unroll
        for (int o = 8; o > 0; o >>= 1) {       // reduce within 16-lane group
            s1 += __shfl_xor_sync(0xffffffffu, s1, o);
            s2 += __shfl_xor_sync(0xffffffffu, s2, o);
        }
        if (tx == 0) { g_ssrc[row] = s1; g_sdst[row] = s2; }
    }
}

// ---------------- kernel 2: per-node softmax aggregation (R9 winner) -------
// One block per node n; warp b handles batch b.
// Pass A: p = exp(lrelu(ssrc+sdst)*w)  (no max pass; |e| small, no overflow).
// Pass B: 8 edges per iteration, 4 LDG.64s in flight, two accumulator chains.
__global__ void __launch_bounds__(256) k_main(float* __restrict__ out) {
    const int n    = blockIdx.x;
    const int b    = threadIdx.x >> 5;
    const int lane = threadIdx.x & 31;

    __shared__ int2 s_dw[CAP];
    __shared__ int2 s_dp[B_SZ][CAP + 8];

    const int deg = min(g_count[n], CAP);   // read BEFORE reset

    for (int i = threadIdx.x; i < deg; i += 256)
        s_dw[i] = g_edge[n * CAP + i];
    __syncthreads();
    if (threadIdx.x == 0) g_count[n] = 0;   // reset for next graph replay

    const float ssrc = g_ssrc[b * N_SZ + n];
    const float* __restrict__ sd = &g_sdst[b * N_SZ];

    // ---- pass A: attention weights (lane-strided) ----
    float denom = 0.f;
    for (int k = lane; k < deg; k += 32) {
        int2  dw = s_dw[k];
        float e  = ssrc + __ldg(&sd[dw.x]);
        e = fmaxf(e, ALPHA * e) * __int_as_float(dw.y);   // leaky relu * w
        float p = __expf(e);
        denom += p;
        s_dp[b][k] = make_int2(dw.x * 128, __float_as_int(p));
    }
#pragma unroll
    for (int o = 16; o > 0; o >>= 1)
        denom += __shfl_xor_sync(0xffffffffu, denom, o);
    if (lane < 8) s_dp[b][deg + lane] = make_int2(0, 0);  // pad: no tail loop
    __syncwarp();

    // ---- pass B: 8 edges/iter, 16 lanes/edge, 4x LDG.64 in flight ----
    const int  sub  = lane >> 4;            // 0: even edge, 1: odd edge
    const char* base = (const char*)(g_Wh2 + (size_t)b * N_SZ * 32)
                     + (lane & 15) * 8;     // 8B fp16 feature slice
    float a0 = 0.f, a1 = 0.f, a2 = 0.f, a3 = 0.f;
    float c0 = 0.f, c1 = 0.f, c2 = 0.f, c3 = 0.f;
    for (int k = 0; k < deg; k += 8) {
        int2 dp0 = s_dp[b][k     + sub];
        int2 dp1 = s_dp[b][k + 2 + sub];
        int2 dp2 = s_dp[b][k + 4 + sub];
        int2 dp3 = s_dp[b][k + 6 + sub];
        uint2 r0 = *(const uint2*)(base + dp0.x);   // 4 independent LDG.64s
        uint2 r1 = *(const uint2*)(base + dp1.x);
        uint2 r2 = *(const uint2*)(base + dp2.x);
        uint2 r3 = *(const uint2*)(base + dp3.x);

        float p0 = __int_as_float(dp0.y);
        float2 f00 = __half22float2(*(const __half2*)&r0.x);
        float2 f01 = __half22float2(*(const __half2*)&r0.y);
        a0 += p0 * f00.x; a1 += p0 * f00.y;
        a2 += p0 * f01.x; a3 += p0 * f01.y;

        float p1 = __int_as_float(dp1.y);
        float2 f10 = __half22float2(*(const __half2*)&r1.x);
        float2 f11 = __half22float2(*(const __half2*)&r1.y);
        c0 += p1 * f10.x; c1 += p1 * f10.y;
        c2 += p1 * f11.x; c3 += p1 * f11.y;

        float p2 = __int_as_float(dp2.y);
        float2 f20 = __half22float2(*(const __half2*)&r2.x);
        float2 f21 = __half22float2(*(const __half2*)&r2.y);
        a0 += p2 * f20.x; a1 += p2 * f20.y;
        a2 += p2 * f21.x; a3 += p2 * f21.y;

        float p3 = __int_as_float(dp3.y);
        float2 f30 = __half22float2(*(const __half2*)&r3.x);
        float2 f31 = __half22float2(*(const __half2*)&r3.y);
        c0 += p3 * f30.x; c1 += p3 * f30.y;
        c2 += p3 * f31.x; c3 += p3 * f31.y;
    }
    a0 += c0; a1 += c1; a2 += c2; a3 += c3;

    // combine the two edge-subsets (lanes l and l+16 hold same features)
    a0 += __shfl_xor_sync(0xffffffffu, a0, 16);
    a1 += __shfl_xor_sync(0xffffffffu, a1, 16);
    a2 += __shfl_xor_sync(0xffffffffu, a2, 16);
    a3 += __shfl_xor_sync(0xffffffffu, a3, 16);

    if (lane < 16) {
        float r0 = 0.f, r1 = 0.f, r2 = 0.f, r3 = 0.f;
        if (deg > 0) {
            float inv = 1.f / denom;
            r0 = a0 * inv; r1 = a1 * inv; r2 = a2 * inv; r3 = a3 * inv;
        }
        // ELU tail: expm1f(x) == __expf(x)-1 to ~6e-8 abs near 0; cheaper
        r0 = r0 > 0.f ? r0 : __expf(r0) - 1.f;
        r1 = r1 > 0.f ? r1 : __expf(r1) - 1.f;
        r2 = r2 > 0.f ? r2 : __expf(r2) - 1.f;
        r3 = r3 > 0.f ? r3 : __expf(r3) - 1.f;
        *(float4*)&out[((size_t)b * N_SZ + n) * 64 + lane * 4]
            = make_float4(r0, r1, r2, r3);
    }
}

// ---------------- launch ---------------------------------------------------
extern "C" void kernel_launch(void* const* d_in, const int* in_sizes, int n_in,
                              void* d_out, int out_size) {
    const float* h  = (const float*)d_in[0];
    const int*   ei = (const int*)  d_in[1];
    const float* ew = (const float*)d_in[2];
    const float* W  = (const float*)d_in[3];
    const float* a  = (const float*)d_in[4];
    float* out = (float*)d_out;

    k_fused<<<GEMM_BLOCKS + SCAT_BLOCKS, 256>>>(h, W, a, ei, ew);
    k_main <<<N_SZ, 256>>>(out);
}